// round 14
// baseline (speedup 1.0000x reference)
#include <cuda_runtime.h>
#include <cuda_bf16.h>
#include <cstdint>

#define SEQ   4096
#define NBATCH 4
#define HD    64
#define DIN   1024
#define MTOT  (NBATCH * SEQ)

// Pre-split projected tensors (written by proj, read by attention)
__device__ __nv_bfloat16 g_Qhi[MTOT * HD], g_Qlo[MTOT * HD];
__device__ __nv_bfloat16 g_Khi[MTOT * HD], g_Klo[MTOT * HD];
__device__ __nv_bfloat16 g_VThi[NBATCH * HD * SEQ], g_VTlo[NBATCH * HD * SEQ];  // [b][dim][key]

// Pre-split W (smem image per (mat, chunk): 64 rows x 64 k, swizzled, 8KB each)
__device__ __nv_bfloat16 g_Wsphi[3 * 16 * 4096], g_Wsplo[3 * 16 * 4096];

__device__ __forceinline__ void split2(float a, float b, uint32_t& hi, uint32_t& lo) {
    __nv_bfloat162 h = __floats2bfloat162_rn(a, b);
    float ra = a - __bfloat162float(h.x);
    float rb = b - __bfloat162float(h.y);
    __nv_bfloat162 l = __floats2bfloat162_rn(ra, rb);
    hi = *(uint32_t*)&h;
    lo = *(uint32_t*)&l;
}

__device__ __forceinline__ void mma16816(float* c, const uint32_t* a, uint32_t b0, uint32_t b1) {
    asm volatile(
        "mma.sync.aligned.m16n8k16.row.col.f32.bf16.bf16.f32 "
        "{%0,%1,%2,%3}, {%4,%5,%6,%7}, {%8,%9}, {%0,%1,%2,%3};"
        : "+f"(c[0]), "+f"(c[1]), "+f"(c[2]), "+f"(c[3])
        : "r"(a[0]), "r"(a[1]), "r"(a[2]), "r"(a[3]), "r"(b0), "r"(b1));
}

__device__ __forceinline__ uint32_t smem_u32(const void* p) {
    uint32_t a;
    asm("{ .reg .u64 t; cvta.to.shared.u64 t, %1; cvt.u32.u64 %0, t; }" : "=r"(a) : "l"(p));
    return a;
}
#define CP_ASYNC16(dst, src) \
    asm volatile("cp.async.cg.shared.global [%0], [%1], 16;" :: "r"(dst), "l"(src) : "memory")
#define CP_COMMIT() asm volatile("cp.async.commit_group;" ::: "memory")
#define CP_WAIT0()  asm volatile("cp.async.wait_group 0;" ::: "memory")

// ===========================================================================
// W pre-split: 3 mats x 16 chunks x 4 quarters -> 192 CTAs (latency spread)
// ===========================================================================
__global__ void presplit_kernel(const float* __restrict__ Wq, const float* __restrict__ Wk,
                                const float* __restrict__ Wv)
{
    const int mat = blockIdx.x, c = blockIdx.y;
    const float* W = (mat == 0) ? Wq : (mat == 1) ? Wk : Wv;
    char* dhi = (char*)(g_Wsphi + (mat * 16 + c) * 4096);
    char* dlo = (char*)(g_Wsplo + (mat * 16 + c) * 4096);
    const int base = blockIdx.z * 1024;
    for (int i = base + threadIdx.x; i < base + 1024; i += 256) {
        int r = i >> 6, k = i & 63;
        float v = W[(size_t)r * DIN + c * 64 + k];
        __nv_bfloat16 h = __float2bfloat16(v);
        int off = r * 128 + (((k >> 3) ^ (r & 7)) << 4) + (k & 7) * 2;
        *(__nv_bfloat16*)(dhi + off) = h;
        *(__nv_bfloat16*)(dlo + off) = __float2bfloat16(v - __bfloat162float(h));
    }
}

// ===========================================================================
// Projection (unchanged from R11): X via fp32 smem split in registers,
// W via pre-split image. M=128, N=64, 16 K-chunks.
// ===========================================================================
#define XBUF(p) ((p) * 32768)
#define WBUF(p) (65536 + (p) * 16384)
#define PROJ_SMEM 98304

__global__ __launch_bounds__(256) void proj_mma_kernel(
    const float* __restrict__ q, const float* __restrict__ k, const float* __restrict__ v)
{
    extern __shared__ char sm[];
    const uint32_t sb = smem_u32(sm);
    const int mat = blockIdx.y;
    const float* __restrict__ x = (mat == 0) ? q : (mat == 1) ? k : v;

    const int t    = threadIdx.x;
    const int w    = t >> 5;
    const int lane = t & 31;
    const int grp  = lane >> 2;
    const int qd   = lane & 3;
    const int m0   = blockIdx.x * 128;
    const int r0   = w * 16 + grp;

    float acc[8][4];
#pragma unroll
    for (int nb = 0; nb < 8; nb++)
#pragma unroll
        for (int j = 0; j < 4; j++) acc[nb][j] = 0.f;

    const int xrow = t >> 4, xk4 = t & 15;

    auto issue_chunk = [&](int c, int p) {
#pragma unroll
        for (int u = 0; u < 8; ++u) {
            int row = xrow + 16 * u;
            uint32_t dst = sb + XBUF(p) + row * 256 + ((xk4 ^ (row & 7)) << 4);
            CP_ASYNC16(dst, x + (size_t)(m0 + row) * DIN + c * 64 + xk4 * 4);
        }
        const char* bh = (const char*)(g_Wsphi + (mat * 16 + c) * 4096);
        const char* bl = (const char*)(g_Wsplo + (mat * 16 + c) * 4096);
#pragma unroll
        for (int u = 0; u < 2; ++u) {
            int idx = t + 256 * u;
            CP_ASYNC16(sb + WBUF(p) + idx * 16, bh + idx * 16);
            CP_ASYNC16(sb + WBUF(p) + 8192 + idx * 16, bl + idx * 16);
        }
        CP_COMMIT();
    };

    issue_chunk(0, 0);

    for (int c = 0; c < 16; ++c) {
        const int p = c & 1;
        CP_WAIT0();
        __syncthreads();
        if (c < 15) issue_chunk(c + 1, p ^ 1);

        const char* xb = sm + XBUF(p);
        const char* wb = sm + WBUF(p);

#pragma unroll
        for (int ks = 0; ks < 4; ++ks) {
            const int k0 = 16 * ks + 2 * qd;
            const int k1 = k0 + 8;
            const int sw0 = (((k0 >> 2) ^ (r0 & 7)) << 4) + (k0 & 3) * 4;
            const int sw1 = (((k1 >> 2) ^ (r0 & 7)) << 4) + (k1 & 3) * 4;
            float2 f0 = *(const float2*)(xb + r0 * 256 + sw0);
            float2 f1 = *(const float2*)(xb + (r0 + 8) * 256 + sw0);
            float2 f2 = *(const float2*)(xb + r0 * 256 + sw1);
            float2 f3 = *(const float2*)(xb + (r0 + 8) * 256 + sw1);
            uint32_t ahi[4], alo[4];
            split2(f0.x, f0.y, ahi[0], alo[0]);
            split2(f1.x, f1.y, ahi[1], alo[1]);
            split2(f2.x, f2.y, ahi[2], alo[2]);
            split2(f3.x, f3.y, ahi[3], alo[3]);
#pragma unroll
            for (int nb = 0; nb < 8; ++nb) {
                const int row = nb * 8 + grp;
                const int sb0 = ((2 * ks) ^ (row & 7)) << 4;
                const int sb1 = ((2 * ks + 1) ^ (row & 7)) << 4;
                uint32_t bh0 = *(const uint32_t*)(wb + row * 128 + sb0 + 4 * qd);
                uint32_t bh1 = *(const uint32_t*)(wb + row * 128 + sb1 + 4 * qd);
                uint32_t bl0 = *(const uint32_t*)(wb + 8192 + row * 128 + sb0 + 4 * qd);
                uint32_t bl1 = *(const uint32_t*)(wb + 8192 + row * 128 + sb1 + 4 * qd);
                mma16816(acc[nb], ahi, bh0, bh1);
                mma16816(acc[nb], alo, bh0, bh1);
                mma16816(acc[nb], ahi, bl0, bl1);
            }
        }
    }

    const int row0 = m0 + r0;
    if (mat < 2) {
        __nv_bfloat16* ohi = (mat == 0) ? g_Qhi : g_Khi;
        __nv_bfloat16* olo = (mat == 0) ? g_Qlo : g_Klo;
#pragma unroll
        for (int nb = 0; nb < 8; ++nb) {
            const int col = nb * 8 + qd * 2;
            uint32_t h0, l0v, h1, l1v;
            split2(acc[nb][0], acc[nb][1], h0, l0v);
            split2(acc[nb][2], acc[nb][3], h1, l1v);
            *(uint32_t*)&ohi[(size_t)row0 * HD + col]       = h0;
            *(uint32_t*)&olo[(size_t)row0 * HD + col]       = l0v;
            *(uint32_t*)&ohi[(size_t)(row0 + 8) * HD + col] = h1;
            *(uint32_t*)&olo[(size_t)(row0 + 8) * HD + col] = l1v;
        }
    } else {
        const int batch = row0 >> 12;
        const int key   = row0 & 4095;
#pragma unroll
        for (int nb = 0; nb < 8; ++nb) {
            const int col = nb * 8 + qd * 2;
#pragma unroll
            for (int ci = 0; ci < 4; ++ci) {
                float val = acc[nb][ci];
                int cc = col + (ci & 1);
                int ky = key + ((ci >> 1) * 8);
                __nv_bfloat16 h = __float2bfloat16(val);
                size_t off = ((size_t)batch * HD + cc) * SEQ + ky;
                g_VThi[off] = h;
                g_VTlo[off] = __float2bfloat16(val - __bfloat162float(h));
            }
        }
    }
}

// ===========================================================================
// Flash attention: cross-iteration pipeline (S one tile ahead), 3-stage
// cp.async ring, exp/split overlapped with PV tensor work, 1 barrier/iter.
// ===========================================================================
#define SQHI 0
#define SQLO 8192
#define SBUF(r) (16384 + (r) * 32768)   // KHI | KLO | VHI | VLO, 8KB each
#define SREDS 114688                     // [4][64] float
#define SO0   16384
#define SO1   33792
#define ATTN_SMEM 115712

__global__ __launch_bounds__(512) void attn_mma_kernel(float* __restrict__ out)
{
    extern __shared__ char sm[];
    const uint32_t sbase = smem_u32(sm);
    float* sRedS = (float*)(sm + SREDS);

    const int b  = blockIdx.y;
    const int pr = blockIdx.x;
    const int t  = threadIdx.x;
    const int w  = t >> 5, lane = t & 31;
    const int wm = w & 3, wn = w >> 2;
    const int grp = lane >> 2, qd = lane & 3;
    const int r0 = 16 * wm + grp;

    const __nv_bfloat16* Qh = g_Qhi + (size_t)b * SEQ * HD;
    const __nv_bfloat16* Ql = g_Qlo + (size_t)b * SEQ * HD;
    const __nv_bfloat16* Kh = g_Khi + (size_t)b * SEQ * HD;
    const __nv_bfloat16* Kl = g_Klo + (size_t)b * SEQ * HD;
    const __nv_bfloat16* Vh = g_VThi + (size_t)b * HD * SEQ;
    const __nv_bfloat16* Vl = g_VTlo + (size_t)b * HD * SEQ;

    const int lrow = t >> 3, lc4 = t & 7;
    const uint32_t ldof = (uint32_t)(lrow * 128 + ((lc4 ^ (lrow & 7)) << 4));

    // fragment smem offsets (depend only on lane ids)
    int chA[4], chB[4];
#pragma unroll
    for (int ks = 0; ks < 4; ++ks) {
        chA[ks] = (((2 * ks) ^ grp) << 4) + qd * 4;
        chB[ks] = (((2 * ks + 1) ^ grp) << 4) + qd * 4;
    }

    for (int half = 0; half < 2; ++half) {
        const int qt = half ? (63 - pr) : pr;

        // ---- issue Q + tile0 (+ tile1)
        CP_ASYNC16(sbase + SQHI + ldof, Qh + (size_t)(qt * 64 + lrow) * HD + lc4 * 8);
        CP_ASYNC16(sbase + SQLO + ldof, Ql + (size_t)(qt * 64 + lrow) * HD + lc4 * 8);
        {
            const uint32_t d0 = sbase + SBUF(0);
            CP_ASYNC16(d0 + ldof,         Kh + (size_t)lrow * HD + lc4 * 8);
            CP_ASYNC16(d0 + 8192 + ldof,  Kl + (size_t)lrow * HD + lc4 * 8);
            CP_ASYNC16(d0 + 16384 + ldof, Vh + (size_t)lrow * SEQ + lc4 * 8);
            CP_ASYNC16(d0 + 24576 + ldof, Vl + (size_t)lrow * SEQ + lc4 * 8);
            CP_COMMIT();
        }
        if (qt >= 1) {
            const uint32_t d1 = sbase + SBUF(1);
            CP_ASYNC16(d1 + ldof,         Kh + (size_t)(64 + lrow) * HD + lc4 * 8);
            CP_ASYNC16(d1 + 8192 + ldof,  Kl + (size_t)(64 + lrow) * HD + lc4 * 8);
            CP_ASYNC16(d1 + 16384 + ldof, Vh + (size_t)lrow * SEQ + 64 + lc4 * 8);
            CP_ASYNC16(d1 + 24576 + ldof, Vl + (size_t)lrow * SEQ + 64 + lc4 * 8);
            CP_COMMIT();
        }
        CP_WAIT0();
        __syncthreads();

        // ---- hoist Q hi fragments only (lo read from smem per use)
        uint32_t qah[4][4];
#pragma unroll
        for (int ks = 0; ks < 4; ++ks) {
            qah[ks][0] = *(uint32_t*)(sm + SQHI + r0 * 128 + chA[ks]);
            qah[ks][1] = *(uint32_t*)(sm + SQHI + (r0 + 8) * 128 + chA[ks]);
            qah[ks][2] = *(uint32_t*)(sm + SQHI + r0 * 128 + chB[ks]);
            qah[ks][3] = *(uint32_t*)(sm + SQHI + (r0 + 8) * 128 + chB[ks]);
        }

        float o[8][4];
#pragma unroll
        for (int nb = 0; nb < 8; ++nb)
#pragma unroll
            for (int j = 0; j < 4; ++j) o[nb][j] = 0.f;
        float lp0 = 0.f, lp1 = 0.f;
        uint32_t ph[4], pl[4];

        // S-compute + exp + split for one tile (kbuf = K tile base)
        auto computeP = [&](const char* kbuf, bool diag) {
            float s[2][4];
#pragma unroll
            for (int nb = 0; nb < 2; ++nb)
#pragma unroll
                for (int j = 0; j < 4; ++j) s[nb][j] = 0.f;
#pragma unroll
            for (int ks = 0; ks < 4; ++ks) {
                uint32_t al[4];
                al[0] = *(uint32_t*)(sm + SQLO + r0 * 128 + chA[ks]);
                al[1] = *(uint32_t*)(sm + SQLO + (r0 + 8) * 128 + chA[ks]);
                al[2] = *(uint32_t*)(sm + SQLO + r0 * 128 + chB[ks]);
                al[3] = *(uint32_t*)(sm + SQLO + (r0 + 8) * 128 + chB[ks]);
#pragma unroll
                for (int nb = 0; nb < 2; ++nb) {
                    const int krow = wn * 16 + nb * 8 + grp;
                    uint32_t bh0 = *(uint32_t*)(kbuf + krow * 128 + chA[ks]);
                    uint32_t bh1 = *(uint32_t*)(kbuf + krow * 128 + chB[ks]);
                    uint32_t bl0 = *(uint32_t*)(kbuf + 8192 + krow * 128 + chA[ks]);
                    uint32_t bl1 = *(uint32_t*)(kbuf + 8192 + krow * 128 + chB[ks]);
                    mma16816(s[nb], qah[ks], bh0, bh1);
                    mma16816(s[nb], al, bh0, bh1);
                    mma16816(s[nb], qah[ks], bl0, bl1);
                }
            }
            const float sc = 0.125f;
            if (diag) {
#pragma unroll
                for (int nb = 0; nb < 2; ++nb) {
                    const int colb = wn * 16 + nb * 8 + 2 * qd;
                    s[nb][0] = (colb     > r0)     ? 0.f : __expf(s[nb][0] * sc);
                    s[nb][1] = (colb + 1 > r0)     ? 0.f : __expf(s[nb][1] * sc);
                    s[nb][2] = (colb     > r0 + 8) ? 0.f : __expf(s[nb][2] * sc);
                    s[nb][3] = (colb + 1 > r0 + 8) ? 0.f : __expf(s[nb][3] * sc);
                }
            } else {
#pragma unroll
                for (int nb = 0; nb < 2; ++nb)
#pragma unroll
                    for (int j = 0; j < 4; ++j) s[nb][j] = __expf(s[nb][j] * sc);
            }
            lp0 += s[0][0] + s[0][1] + s[1][0] + s[1][1];
            lp1 += s[0][2] + s[0][3] + s[1][2] + s[1][3];
            split2(s[0][0], s[0][1], ph[0], pl[0]);
            split2(s[0][2], s[0][3], ph[1], pl[1]);
            split2(s[1][0], s[1][1], ph[2], pl[2]);
            split2(s[1][2], s[1][3], ph[3], pl[3]);
        };

        // ---- preamble: P(0)
        computeP(sm + SBUF(0), qt == 0);

        const int cb0 = (((2 * wn) ^ grp) << 4) + qd * 4;
        const int cb1 = (((2 * wn + 1) ^ grp) << 4) + qd * 4;

        for (int kt = 0; kt <= qt; ++kt) {
            if (kt > 0) {
                CP_WAIT0();
                __syncthreads();   // tile kt+1 visible; all warps done with iter kt-1
            }
            // prefetch tile kt+2 into ring slot (its old contents consumed)
            if (kt + 2 <= qt) {
                const uint32_t dst = sbase + SBUF((kt + 2) % 3);
                CP_ASYNC16(dst + ldof,         Kh + (size_t)((kt + 2) * 64 + lrow) * HD + lc4 * 8);
                CP_ASYNC16(dst + 8192 + ldof,  Kl + (size_t)((kt + 2) * 64 + lrow) * HD + lc4 * 8);
                CP_ASYNC16(dst + 16384 + ldof, Vh + (size_t)lrow * SEQ + (kt + 2) * 64 + lc4 * 8);
                CP_ASYNC16(dst + 24576 + ldof, Vl + (size_t)lrow * SEQ + (kt + 2) * 64 + lc4 * 8);
                CP_COMMIT();
            }

            const char* bufX = sm + SBUF(kt % 3);
            // capture current P fragments (computeP below overwrites ph/pl)
            uint32_t cph[4] = {ph[0], ph[1], ph[2], ph[3]};
            uint32_t cpl[4] = {pl[0], pl[1], pl[2], pl[3]};

            // ---- S(kt+1) ahead of PV(kt): its MMAs issue first, exp later
            if (kt < qt) computeP(sm + SBUF((kt + 1) % 3), kt + 1 == qt);

            // ---- O += P(kt) V(kt)
#pragma unroll
            for (int nb = 0; nb < 8; ++nb) {
                const int vrow = nb * 8 + grp;
                uint32_t vh0 = *(uint32_t*)(bufX + 16384 + vrow * 128 + cb0);
                uint32_t vh1 = *(uint32_t*)(bufX + 16384 + vrow * 128 + cb1);
                uint32_t vl0 = *(uint32_t*)(bufX + 24576 + vrow * 128 + cb0);
                uint32_t vl1 = *(uint32_t*)(bufX + 24576 + vrow * 128 + cb1);
                mma16816(o[nb], cph, vh0, vh1);
                mma16816(o[nb], cpl, vh0, vh1);
                mma16816(o[nb], cph, vl0, vl1);
            }
        }  // kt

        // ---- l reduction (once per q-tile)
        lp0 += __shfl_xor_sync(0xffffffffu, lp0, 1);
        lp0 += __shfl_xor_sync(0xffffffffu, lp0, 2);
        lp1 += __shfl_xor_sync(0xffffffffu, lp1, 1);
        lp1 += __shfl_xor_sync(0xffffffffu, lp1, 2);
        if (qd == 0) { sRedS[wn * 64 + r0] = lp0; sRedS[wn * 64 + r0 + 8] = lp1; }
        __syncthreads();
        const float l0 = sRedS[r0] + sRedS[64 + r0] + sRedS[128 + r0] + sRedS[192 + r0];
        const float l1 = sRedS[r0 + 8] + sRedS[64 + r0 + 8]
                       + sRedS[128 + r0 + 8] + sRedS[192 + r0 + 8];

        // ---- merge 4 key-quarter partials, normalize, write
        float* sO0 = (float*)(sm + SO0);
        float* sO1 = (float*)(sm + SO1);
        if (wn == 0 || wn == 2) {
            float* d = (wn == 0) ? sO0 : sO1;
#pragma unroll
            for (int nb = 0; nb < 8; ++nb) {
                const int col = nb * 8 + 2 * qd;
                *(float2*)&d[r0 * 66 + col]       = make_float2(o[nb][0], o[nb][1]);
                *(float2*)&d[(r0 + 8) * 66 + col] = make_float2(o[nb][2], o[nb][3]);
            }
        }
        __syncthreads();
        if (wn == 1) {
#pragma unroll
            for (int nb = 0; nb < 8; ++nb) {
                const int col = nb * 8 + 2 * qd;
                float2 p0 = *(float2*)&sO0[r0 * 66 + col];
                float2 p1 = *(float2*)&sO0[(r0 + 8) * 66 + col];
                *(float2*)&sO0[r0 * 66 + col]       = make_float2(p0.x + o[nb][0], p0.y + o[nb][1]);
                *(float2*)&sO0[(r0 + 8) * 66 + col] = make_float2(p1.x + o[nb][2], p1.y + o[nb][3]);
            }
        }
        if (wn == 3) {
#pragma unroll
            for (int nb = 0; nb < 8; ++nb) {
                const int col = nb * 8 + 2 * qd;
                float2 p0 = *(float2*)&sO1[r0 * 66 + col];
                float2 p1 = *(float2*)&sO1[(r0 + 8) * 66 + col];
                o[nb][0] += p0.x; o[nb][1] += p0.y;
                o[nb][2] += p1.x; o[nb][3] += p1.y;
            }
        }
        __syncthreads();
        if (wn == 3) {
            const float i0 = 1.f / l0, i1 = 1.f / l1;
            float* orow0 = out + ((size_t)b * SEQ + qt * 64 + r0) * HD;
            float* orow1 = orow0 + 8 * HD;
#pragma unroll
            for (int nb = 0; nb < 8; ++nb) {
                const int col = nb * 8 + 2 * qd;
                float2 p0 = *(float2*)&sO0[r0 * 66 + col];
                float2 p1 = *(float2*)&sO0[(r0 + 8) * 66 + col];
                *(float2*)&orow0[col] = make_float2((p0.x + o[nb][0]) * i0, (p0.y + o[nb][1]) * i0);
                *(float2*)&orow1[col] = make_float2((p1.x + o[nb][2]) * i1, (p1.y + o[nb][3]) * i1);
            }
        }
        __syncthreads();
    }  // half
}

// ---------------------------------------------------------------------------
extern "C" void kernel_launch(void* const* d_in, const int* in_sizes, int n_in,
                              void* d_out, int out_size)
{
    const float* q  = (const float*)d_in[0];
    const float* k  = (const float*)d_in[1];
    const float* v  = (const float*)d_in[2];
    const float* Wq = (const float*)d_in[3];
    const float* Wk = (const float*)d_in[4];
    const float* Wv = (const float*)d_in[5];
    float* out = (float*)d_out;

    cudaFuncSetAttribute(proj_mma_kernel, cudaFuncAttributeMaxDynamicSharedMemorySize, PROJ_SMEM);
    cudaFuncSetAttribute(attn_mma_kernel, cudaFuncAttributeMaxDynamicSharedMemorySize, ATTN_SMEM);

    dim3 wgrid(3, 16, 4);
    presplit_kernel<<<wgrid, 256>>>(Wq, Wk, Wv);

    dim3 pgrid(128, 3);
    proj_mma_kernel<<<pgrid, 256, PROJ_SMEM>>>(q, k, v);

    dim3 agrid(32, NBATCH);
    attn_mma_kernel<<<agrid, 512, ATTN_SMEM>>>(out);
}